// round 6
// baseline (speedup 1.0000x reference)
#include <cuda_runtime.h>
#include <cuda_fp16.h>

#define SB   32      // S*B
#define NTOK 2048    // N
#define KK   16      // K
#define DD   32      // D
#define HH   128     // H

#define TPB   128    // threads per block (4 warps)
#define TOKPB 32     // tokens per block (1 per lane; warp = h-slice of 32)

typedef unsigned long long u64;

// Scratch for hk[k,h] + b1[h] per (s,b). 32*16*128 floats = 256 KB.
__device__ float g_hkb[SB * KK * HH];

__device__ __forceinline__ u64 pk2(float lo, float hi) {
    u64 r; asm("mov.b64 %0, {%1, %2};" : "=l"(r) : "f"(lo), "f"(hi)); return r;
}
__device__ __forceinline__ void upk2(float& lo, float& hi, u64 v) {
    asm("mov.b64 {%0, %1}, %2;" : "=f"(lo), "=f"(hi) : "l"(v));
}
__device__ __forceinline__ u64 add2(u64 a, u64 b) {
    u64 r; asm("add.rn.f32x2 %0, %1, %2;" : "=l"(r) : "l"(a), "l"(b)); return r;
}
__device__ __forceinline__ u64 fma2(u64 a, u64 b, u64 c) {
    u64 r; asm("fma.rn.f32x2 %0, %1, %2, %3;" : "=l"(r) : "l"(a), "l"(b), "l"(c)); return r;
}
// tanh on a packed half2 — one MUFU op for two values.
__device__ __forceinline__ __half2 tanh2(__half2 v) {
    unsigned vi = *reinterpret_cast<unsigned*>(&v), yi;
    asm("tanh.approx.f16x2 %0, %1;" : "=r"(yi) : "r"(vi));
    return *reinterpret_cast<__half2*>(&yi);
}

// ---------------------------------------------------------------------------
// Prep: hkb[sb,k,h] = sum_d mu[sb,k,d]*Wm[d,h] + tau[sb,k,d]*Wt[d,h] + b1[h]
// ---------------------------------------------------------------------------
__global__ void prep_kernel(const float* __restrict__ mu,
                            const float* __restrict__ tau,
                            const float* __restrict__ W1,
                            const float* __restrict__ b1) {
    int k  = blockIdx.x;
    int sb = blockIdx.y;
    int h  = threadIdx.x;
    const float* mur  = mu  + (sb * KK + k) * DD;
    const float* taur = tau + (sb * KK + k) * DD;
    float s = b1[h];
    #pragma unroll
    for (int d = 0; d < DD; d++) {
        s = fmaf(mur [d], W1[(DD     + d) * HH + h], s);
        s = fmaf(taur[d], W1[(2 * DD + d) * HH + h], s);
    }
    g_hkb[(sb * KK + k) * HH + h] = s;
}

// ---------------------------------------------------------------------------
// Main: block = 4 warps x 32 tokens. Warp w owns h-slice [32w, 32w+32);
// lane = token.
//   Phase A (f32): hx2[16] via 16 independent FFMA2 chains.
//   Phase B: per k: 8 broadcast LDS.128 + 16 ADD2 (f32) + 16 F2FP pack
//            + 16 tanh.f16x2 (MUFU halved) + 16 HFMA2 into 4 half2 accs,
//            reduced to f32.
// ---------------------------------------------------------------------------
__global__ __launch_bounds__(TPB, 6)
void main_kernel(const float* __restrict__ x,
                 const float* __restrict__ W1,
                 const float* __restrict__ W2,
                 float* __restrict__ out) {
    __shared__ float Wx_s[DD * HH];             // 16 KB
    __shared__ float hkb_s[KK * HH];            //  8 KB
    __shared__ float w2_s[HH];                  // 0.5 KB
    __shared__ float part_s[4][TOKPB][KK + 1];  //  8.5 KB, padded rows

    const int tid  = threadIdx.x;
    const int w    = tid >> 5;                  // warp id = h-slice
    const int lane = tid & 31;                  // token within block
    const int sb   = blockIdx.y;
    const int n    = blockIdx.x * TOKPB + lane;

    for (int i = tid; i < DD * HH; i += TPB) Wx_s[i]  = W1[i];   // rows 0..31 of W1
    for (int i = tid; i < KK * HH; i += TPB) hkb_s[i] = g_hkb[sb * KK * HH + i];
    if (tid < HH) w2_s[tid] = W2[tid];
    __syncthreads();

    // x row (32 floats) into registers
    float xr[DD];
    const float4* xp = reinterpret_cast<const float4*>(x + ((size_t)sb * NTOK + n) * DD);
    #pragma unroll
    for (int i = 0; i < 8; i++) {
        float4 v = xp[i];
        xr[4 * i + 0] = v.x; xr[4 * i + 1] = v.y;
        xr[4 * i + 2] = v.z; xr[4 * i + 3] = v.w;
    }

    const int h0 = w * 32;

    // ---- Phase A: hx for the full 32-h slice (16 f32x2 chains) ----
    u64 hx2[16];
    #pragma unroll
    for (int j = 0; j < 16; j++) hx2[j] = 0ull;

    #pragma unroll
    for (int d = 0; d < DD; d++) {
        u64 xd2 = pk2(xr[d], xr[d]);
        const ulonglong2* wrow = reinterpret_cast<const ulonglong2*>(&Wx_s[d * HH + h0]);
        #pragma unroll
        for (int q = 0; q < 8; q++) {
            ulonglong2 wv = wrow[q];          // warp-uniform broadcast LDS.128
            hx2[2 * q + 0] = fma2(xd2, wv.x, hx2[2 * q + 0]);
            hx2[2 * q + 1] = fma2(xd2, wv.y, hx2[2 * q + 1]);
        }
    }

    // W2 slice as half2 pairs (w2h[2q]   = (w2[4q],   w2[4q+1]),
    //                          w2h[2q+1] = (w2[4q+2], w2[4q+3]))
    __half2 w2h[16];
    {
        const float4* w2p = reinterpret_cast<const float4*>(&w2_s[h0]);
        #pragma unroll
        for (int q = 0; q < 8; q++) {
            float4 wv = w2p[q];
            w2h[2 * q + 0] = __floats2half2_rn(wv.x, wv.y);
            w2h[2 * q + 1] = __floats2half2_rn(wv.z, wv.w);
        }
    }

    // ---- Phase B: k-sweep, tanh in f16x2 ----
    float acc[KK];
    #pragma unroll
    for (int k = 0; k < KK; k++) {
        const ulonglong2* hkp = reinterpret_cast<const ulonglong2*>(&hkb_s[k * HH + h0]);
        __half2 a0 = __float2half2_rn(0.f), a1 = a0, a2 = a0, a3 = a0;
        #pragma unroll
        for (int q = 0; q < 8; q++) {
            ulonglong2 hv = hkp[q];           // warp-uniform broadcast LDS.128
            u64 t0 = add2(hx2[2 * q + 0], hv.x);   // f32 precision sum
            u64 t1 = add2(hx2[2 * q + 1], hv.y);
            float l0, g0, l1, g1;
            upk2(l0, g0, t0);
            upk2(l1, g1, t1);
            __half2 th0 = tanh2(__floats2half2_rn(l0, g0));  // 1 F2FP + 1 MUFU
            __half2 th1 = tanh2(__floats2half2_rn(l1, g1));
            if (q & 1) { a2 = __hfma2(th0, w2h[2 * q + 0], a2);
                         a3 = __hfma2(th1, w2h[2 * q + 1], a3); }
            else       { a0 = __hfma2(th0, w2h[2 * q + 0], a0);
                         a1 = __hfma2(th1, w2h[2 * q + 1], a1); }
        }
        float2 f01 = __half22float2(__hadd2(a0, a1));
        float2 f23 = __half22float2(__hadd2(a2, a3));
        acc[k] = (f01.x + f01.y) + (f23.x + f23.y);
    }

    // Stage partial gammas (scalar, padded row of 17 -> conflict-free).
    #pragma unroll
    for (int k = 0; k < KK; k++) part_s[w][lane][k] = acc[k];
    __syncthreads();

    // Reduce + softmax: thread t handles token (t>>2), k-quad (t&3).
    const int tok = tid >> 2;
    const int kq  = tid & 3;
    float g[4];
    #pragma unroll
    for (int j = 0; j < 4; j++) {
        int k = 4 * kq + j;
        g[j] = ((part_s[0][tok][k] + part_s[1][tok][k]) +
                (part_s[2][tok][k] + part_s[3][tok][k]));
    }

    float m = fmaxf(fmaxf(g[0], g[1]), fmaxf(g[2], g[3]));
    m = fmaxf(m, __shfl_xor_sync(0xffffffffu, m, 1));
    m = fmaxf(m, __shfl_xor_sync(0xffffffffu, m, 2));

    float e0 = __expf(g[0] - m), e1 = __expf(g[1] - m);
    float e2 = __expf(g[2] - m), e3 = __expf(g[3] - m);
    float s = (e0 + e1) + (e2 + e3);
    s += __shfl_xor_sync(0xffffffffu, s, 1);
    s += __shfl_xor_sync(0xffffffffu, s, 2);
    float inv = __fdividef(1.f, s);

    const int ntok = blockIdx.x * TOKPB + tok;
    float4 o;
    o.x = e0 * inv; o.y = e1 * inv; o.z = e2 * inv; o.w = e3 * inv;
    reinterpret_cast<float4*>(out + ((size_t)sb * NTOK + ntok) * KK)[kq] = o;
}

extern "C" void kernel_launch(void* const* d_in, const int* in_sizes, int n_in,
                              void* d_out, int out_size) {
    const float* x   = (const float*)d_in[0];
    const float* mu  = (const float*)d_in[1];
    const float* tau = (const float*)d_in[2];
    const float* W1  = (const float*)d_in[3];
    const float* b1  = (const float*)d_in[4];
    const float* W2  = (const float*)d_in[5];
    // d_in[6] = b2: cancels in softmax, unused.
    float* out = (float*)d_out;

    prep_kernel<<<dim3(KK, SB), HH>>>(mu, tau, W1, b1);
    main_kernel<<<dim3(NTOK / TOKPB, SB), TPB>>>(x, W1, W2, out);
}